// round 9
// baseline (speedup 1.0000x reference)
#include <cuda_runtime.h>

// SNN + STDP scan, 256 steps, 784 inputs, 512 neurons.
// R8: SPECULATIVE dual-branch execution. spk(t) is one bit; both candidate
// W-updates and both next-step dot partials (p0,p1) are computed BEFORE I(t)
// arrives, overlapped with the butterfly + barrier wait. Post-barrier chain is
// just LDS -> I -> LIF fma -> setp -> selp(p) -> next butterfly. The selected
// W is rematerialized with one select of (am, ltp-base) + 8 sat-FMAs, bitwise
// identical to the R6 arithmetic. Candidates are transient registers.

namespace {
constexpr int   T_STEPS = 256;
constexpr int   D_IN    = 784;
constexpr int   N_NEUR  = 512;
constexpr int   CHUNKS  = D_IN / 4;   // 196 float4 per row
constexpr int   WPN     = 4;
constexpr int   NPB     = 4;
constexpr int   KMAX    = 2;
constexpr float ALPHA      = 0.9f;
constexpr float BETA       = 0.8f;
constexpr float THRESHOLD  = 1.0f;
constexpr float BETA_PLUS  = 0.9f;
constexpr float BETA_MINUS = 0.9f;
constexpr float A_PLUS     = 0.008f;
constexpr float A_MINUS    = 0.0066f;
}

using u64 = unsigned long long;

__device__ __forceinline__ u64 pk2(float lo, float hi) {
    u64 r; asm("mov.b64 %0, {%1, %2};" : "=l"(r) : "f"(lo), "f"(hi)); return r;
}
__device__ __forceinline__ void upk2(u64 v, float& lo, float& hi) {
    asm("mov.b64 {%0, %1}, %2;" : "=f"(lo), "=f"(hi) : "l"(v));
}
__device__ __forceinline__ u64 ffma2(u64 a, u64 b, u64 c) {
    u64 d; asm("fma.rn.f32x2 %0, %1, %2, %3;" : "=l"(d) : "l"(a), "l"(b), "l"(c));
    return d;
}
__device__ __forceinline__ void neuron_bar(int id) {
    asm volatile("bar.sync %0, 128;" :: "r"(id) : "memory");
}
__device__ __forceinline__ void stg_cs_v2b64(void* p, u64 a, u64 b) {
    asm volatile("st.global.cs.v2.b64 [%0], {%1, %2};" :: "l"(p), "l"(a), "l"(b) : "memory");
}

__global__ __launch_bounds__(512, 1)
void snn_spec(const float* __restrict__ image,
              const float* __restrict__ W0,
              float* __restrict__ out)
{
    const int tid   = threadIdx.x;
    const int lane  = tid & 31;
    const int warp  = tid >> 5;
    const int group = warp >> 2;         // neuron slot, 0..3
    const int wing  = warp & 3;          // warp-in-neuron
    const int n     = blockIdx.x * NPB + group;
    const int barid = group + 1;

    const int  c0  = (wing << 5) + lane;
    const int  c1  = c0 + 128;
    const bool k1v = (c1 < CHUNKS);

    const float4 f4z = make_float4(0.f, 0.f, 0.f, 0.f);
    const u64 AP2 = pk2(A_PLUS, A_PLUS);
    const u64 BP2 = pk2(BETA_PLUS, BETA_PLUS);

    u64 w01[KMAX], w23[KMAX], pre01[KMAX], pre23[KMAX];
    u64 xc01[KMAX], xc23[KMAX], xn01[KMAX], xn23[KMAX];

    {   // load W row (packed)
        const float4* wrow = reinterpret_cast<const float4*>(W0) + (size_t)n * CHUNKS;
        float4 t0 = __ldg(wrow + c0);
        float4 t1 = k1v ? __ldg(wrow + c1) : f4z;
        w01[0] = pk2(t0.x, t0.y);  w23[0] = pk2(t0.z, t0.w);
        w01[1] = pk2(t1.x, t1.y);  w23[1] = pk2(t1.z, t1.w);
    }
    #pragma unroll
    for (int k = 0; k < KMAX; ++k) { pre01[k] = 0ull; pre23[k] = 0ull; }

    {   // prefetch x_0, x_1 (packed)
        const float4* xrow = reinterpret_cast<const float4*>(image);
        float4 a0 = __ldg(xrow + c0);
        float4 a1 = k1v ? __ldg(xrow + c1) : f4z;
        float4 b0 = __ldg(xrow + CHUNKS + c0);
        float4 b1 = k1v ? __ldg(xrow + CHUNKS + c1) : f4z;
        xc01[0] = pk2(a0.x, a0.y); xc23[0] = pk2(a0.z, a0.w);
        xc01[1] = pk2(a1.x, a1.y); xc23[1] = pk2(a1.z, a1.w);
        xn01[0] = pk2(b0.x, b0.y); xn23[0] = pk2(b0.z, b0.w);
        xn01[1] = pk2(b1.x, b1.y); xn23[1] = pk2(b1.z, b1.w);
    }
    const float4* xpf = reinterpret_cast<const float4*>(image) + 2 * (size_t)CHUNKS;

    // ---- prologue: per-lane partial of W0 . x_0 ----
    float p;
    {
        u64 m01 = ffma2(w01[0], xc01[0], 0ull);
        m01     = ffma2(w01[1], xc01[1], m01);
        u64 m23 = ffma2(w23[0], xc23[0], 0ull);
        m23     = ffma2(w23[1], xc23[1], m23);
        float aa, ab, ac, ad;
        upk2(m01, aa, ab); upk2(m23, ac, ad);
        p = (aa + ab) + (ac + ad);
    }

    __shared__ float part1[2][NPB][WPN];

    float syn = 0.f, mem = 0.f, spk_prev = 0.f, post = 0.f;

    float* __restrict__ spkrec  = out + (size_t)T_STEPS * N_NEUR * D_IN;
    float* __restrict__ memrec  = spkrec  + T_STEPS * N_NEUR;
    float* __restrict__ synrec  = memrec  + T_STEPS * N_NEUR;
    float* __restrict__ postrec = synrec  + T_STEPS * N_NEUR;

    float4* wptr = reinterpret_cast<float4*>(out) + (size_t)n * CHUNKS;
    int sidx = n;

    for (int t = 0; t < T_STEPS; ++t) {
        const int buf = t & 1;

        // ---- butterfly on this step's partial (long pole starts first) ----
        float r = p;
        #pragma unroll
        for (int s = 1; s < 32; s <<= 1)
            r += __shfl_xor_sync(0xffffffffu, r, s);
        if (lane == 0) part1[buf][group][wing] = r;

        // ======== SPECULATIVE BLOCK (independent of I; fills shfl/bar wait) ====
        // Branch 0 (spk=0): post0 = bm*post,      am0 = -A_MINUS*post0, no LTP
        // Branch 1 (spk=1): post1 = fma(bm,post,1), am1 = -A_MINUS*post1, LTP
        const float post0 = BETA_MINUS * post;
        const float post1 = fmaf(BETA_MINUS, post, 1.0f);
        const float am0   = -(A_MINUS * post0);
        const float am1   = -(A_MINUS * post1);

        u64 lw01[KMAX], lw23[KMAX];          // ltp base: A_PLUS*pre + w
        u64 d0a = 0ull, d0b = 0ull, d1a = 0ull, d1b = 0ull;
        #pragma unroll
        for (int k = 0; k < KMAX; ++k) {
            lw01[k] = ffma2(AP2, pre01[k], w01[k]);
            lw23[k] = ffma2(AP2, pre23[k], w23[k]);

            float wx, wy, wz, ww, lx, ly, lz, lwv, xx, xy, xz, xw;
            upk2(w01[k], wx, wy);   upk2(w23[k], wz, ww);
            upk2(lw01[k], lx, ly);  upk2(lw23[k], lz, lwv);
            upk2(xc01[k], xx, xy);  upk2(xc23[k], xz, xw);

            // candidate spk=0
            const u64 v0a = pk2(__saturatef(fmaf(am0, xx, wx)),
                                __saturatef(fmaf(am0, xy, wy)));
            const u64 v0b = pk2(__saturatef(fmaf(am0, xz, wz)),
                                __saturatef(fmaf(am0, xw, ww)));
            // candidate spk=1
            const u64 v1a = pk2(__saturatef(fmaf(am1, xx, lx)),
                                __saturatef(fmaf(am1, xy, ly)));
            const u64 v1b = pk2(__saturatef(fmaf(am1, xz, lz)),
                                __saturatef(fmaf(am1, xw, lwv)));

            // both candidate dots with x_{t+1} (candidates die here)
            d0a = ffma2(v0a, xn01[k], d0a);
            d0b = ffma2(v0b, xn23[k], d0b);
            d1a = ffma2(v1a, xn01[k], d1a);
            d1b = ffma2(v1b, xn23[k], d1b);

            // pre-trace recurrence (pre consumed by lw already)
            pre01[k] = ffma2(BP2, pre01[k], xc01[k]);
            pre23[k] = ffma2(BP2, pre23[k], xc23[k]);
        }
        float p0, p1;
        {
            float a0, b0_, c0_, d0_, a1, b1_, c1_, d1_;
            upk2(d0a, a0, b0_); upk2(d0b, c0_, d0_);
            upk2(d1a, a1, b1_); upk2(d1b, c1_, d1_);
            p0 = (a0 + b0_) + (c0_ + d0_);
            p1 = (a1 + b1_) + (c1_ + d1_);
        }
        // ======== END SPECULATIVE BLOCK =======================================

        neuron_bar(barid);

        // ---- combine: I, LIF, spike decision, select speculated results ----
        const float* q = part1[buf][group];
        const float I = (q[0] + q[1]) + (q[2] + q[3]);

        syn = fmaf(ALPHA, syn, I);
        mem = fmaf(BETA, mem, syn) - spk_prev * THRESHOLD;
        const bool  spkb = (mem > THRESHOLD);
        const float spk  = spkb ? 1.0f : 0.0f;

        p    = spkb ? p1 : p0;          // next step's partial: chain done here
        post = spkb ? post1 : post0;

        // ---- rematerialize selected W (bitwise = R6 path), store W_rec[t] ----
        const float am_s = spkb ? am1 : am0;
        #pragma unroll
        for (int k = 0; k < KMAX; ++k) {
            const u64 b01 = spkb ? lw01[k] : w01[k];
            const u64 b23 = spkb ? lw23[k] : w23[k];
            float bx, by, bz, bw, xx, xy, xz, xw;
            upk2(b01, bx, by); upk2(b23, bz, bw);
            upk2(xc01[k], xx, xy); upk2(xc23[k], xz, xw);
            w01[k] = pk2(__saturatef(fmaf(am_s, xx, bx)),
                         __saturatef(fmaf(am_s, xy, by)));
            w23[k] = pk2(__saturatef(fmaf(am_s, xz, bz)),
                         __saturatef(fmaf(am_s, xw, bw)));
            const bool act = (k == 0) || k1v;
            const int  c   = (k == 0) ? c0 : c1;
            if (act) stg_cs_v2b64(wptr + c, w01[k], w23[k]);

            // rotate x, prefetch x_{t+2}
            xc01[k] = xn01[k]; xc23[k] = xn23[k];
            if (act && (t + 2 < T_STEPS)) {
                float4 xt = __ldg(xpf + c);
                xn01[k] = pk2(xt.x, xt.y);
                xn23[k] = pk2(xt.z, xt.w);
            }
        }

        // ---- scalar records (one thread per neuron) ----
        if (wing == 0 && lane == 0) {
            spkrec[sidx]  = spk;
            memrec[sidx]  = mem;
            synrec[sidx]  = syn;
            postrec[sidx] = post;
        }

        spk_prev = spk;
        wptr += (size_t)N_NEUR * CHUNKS;
        xpf  += CHUNKS;
        sidx += N_NEUR;
    }
}

extern "C" void kernel_launch(void* const* d_in, const int* in_sizes, int n_in,
                              void* d_out, int out_size)
{
    const float* image = (const float*)d_in[0];  // [256, 784] f32
    const float* W     = (const float*)d_in[1];  // [512, 784] f32
    float* out = (float*)d_out;
    (void)in_sizes; (void)n_in; (void)out_size;
    snn_spec<<<N_NEUR / NPB, NPB * WPN * 32>>>(image, W, out);
}

// round 10
// speedup vs baseline: 1.5513x; 1.5513x over previous
#include <cuda_runtime.h>

// SNN + STDP scan, 256 steps, 784 inputs, 512 neurons.
// R9 = R7 structure + PREDICTED speculation (spk=1 is taken ~always since
// I ~ 39 >> threshold=1). The spk=1 W-update, next-step dot p1, and post1 are
// computed BEFORE the barrier (same instr count as R7, just hoisted), hidden
// under the shfl butterfly + barrier wait. Post-barrier fast path: verify and
// commit (register renames). Mispredict -> warp-uniform slow path recomputes
// the spk=0 update + dot (bit-exact with R6/R7 arithmetic on both paths).

namespace {
constexpr int   T_STEPS = 256;
constexpr int   D_IN    = 784;
constexpr int   N_NEUR  = 512;
constexpr int   CHUNKS  = D_IN / 4;   // 196 float4 per row
constexpr int   WPN     = 4;
constexpr int   NPB     = 4;
constexpr int   KMAX    = 2;
constexpr float ALPHA      = 0.9f;
constexpr float BETA       = 0.8f;
constexpr float THRESHOLD  = 1.0f;
constexpr float BETA_PLUS  = 0.9f;
constexpr float BETA_MINUS = 0.9f;
constexpr float A_PLUS     = 0.008f;
constexpr float A_MINUS    = 0.0066f;
}

using u64 = unsigned long long;

__device__ __forceinline__ u64 pk2(float lo, float hi) {
    u64 r; asm("mov.b64 %0, {%1, %2};" : "=l"(r) : "f"(lo), "f"(hi)); return r;
}
__device__ __forceinline__ void upk2(u64 v, float& lo, float& hi) {
    asm("mov.b64 {%0, %1}, %2;" : "=f"(lo), "=f"(hi) : "l"(v));
}
__device__ __forceinline__ u64 ffma2(u64 a, u64 b, u64 c) {
    u64 d; asm("fma.rn.f32x2 %0, %1, %2, %3;" : "=l"(d) : "l"(a), "l"(b), "l"(c));
    return d;
}
__device__ __forceinline__ void neuron_bar(int id) {
    asm volatile("bar.sync %0, 128;" :: "r"(id) : "memory");
}
__device__ __forceinline__ void stg_cs_v2b64(void* p, u64 a, u64 b) {
    asm volatile("st.global.cs.v2.b64 [%0], {%1, %2};" :: "l"(p), "l"(a), "l"(b) : "memory");
}

__global__ __launch_bounds__(512, 1)
void snn_pred(const float* __restrict__ image,
              const float* __restrict__ W0,
              float* __restrict__ out)
{
    const int tid   = threadIdx.x;
    const int lane  = tid & 31;
    const int warp  = tid >> 5;
    const int group = warp >> 2;         // neuron slot, 0..3
    const int wing  = warp & 3;          // warp-in-neuron
    const int n     = blockIdx.x * NPB + group;
    const int barid = group + 1;

    const int  c0  = (wing << 5) + lane;
    const int  c1  = c0 + 128;
    const bool k1v = (c1 < CHUNKS);

    const float4 f4z = make_float4(0.f, 0.f, 0.f, 0.f);
    const u64 AP2 = pk2(A_PLUS, A_PLUS);
    const u64 BP2 = pk2(BETA_PLUS, BETA_PLUS);

    u64 w01[KMAX], w23[KMAX], pre01[KMAX], pre23[KMAX];
    u64 xc01[KMAX], xc23[KMAX], xn01[KMAX], xn23[KMAX];

    {   // load W row (packed)
        const float4* wrow = reinterpret_cast<const float4*>(W0) + (size_t)n * CHUNKS;
        float4 t0 = __ldg(wrow + c0);
        float4 t1 = k1v ? __ldg(wrow + c1) : f4z;
        w01[0] = pk2(t0.x, t0.y);  w23[0] = pk2(t0.z, t0.w);
        w01[1] = pk2(t1.x, t1.y);  w23[1] = pk2(t1.z, t1.w);
    }
    #pragma unroll
    for (int k = 0; k < KMAX; ++k) { pre01[k] = 0ull; pre23[k] = 0ull; }

    {   // prefetch x_0, x_1 (packed)
        const float4* xrow = reinterpret_cast<const float4*>(image);
        float4 a0 = __ldg(xrow + c0);
        float4 a1 = k1v ? __ldg(xrow + c1) : f4z;
        float4 b0 = __ldg(xrow + CHUNKS + c0);
        float4 b1 = k1v ? __ldg(xrow + CHUNKS + c1) : f4z;
        xc01[0] = pk2(a0.x, a0.y); xc23[0] = pk2(a0.z, a0.w);
        xc01[1] = pk2(a1.x, a1.y); xc23[1] = pk2(a1.z, a1.w);
        xn01[0] = pk2(b0.x, b0.y); xn23[0] = pk2(b0.z, b0.w);
        xn01[1] = pk2(b1.x, b1.y); xn23[1] = pk2(b1.z, b1.w);
    }
    const float4* xpf = reinterpret_cast<const float4*>(image) + 2 * (size_t)CHUNKS;

    // ---- prologue: per-lane partial of W0 . x_0 ----
    float p;
    {
        u64 m01 = ffma2(w01[0], xc01[0], 0ull);
        m01     = ffma2(w01[1], xc01[1], m01);
        u64 m23 = ffma2(w23[0], xc23[0], 0ull);
        m23     = ffma2(w23[1], xc23[1], m23);
        float aa, ab, ac, ad;
        upk2(m01, aa, ab); upk2(m23, ac, ad);
        p = (aa + ab) + (ac + ad);
    }

    __shared__ float4 part4[2][NPB];

    float syn = 0.f, mem = 0.f, spk_prev = 0.f, post = 0.f;

    float* __restrict__ spkrec  = out + (size_t)T_STEPS * N_NEUR * D_IN;
    float* __restrict__ memrec  = spkrec  + T_STEPS * N_NEUR;
    float* __restrict__ synrec  = memrec  + T_STEPS * N_NEUR;
    float* __restrict__ postrec = synrec  + T_STEPS * N_NEUR;

    float4* wptr = reinterpret_cast<float4*>(out) + (size_t)n * CHUNKS;
    int sidx = n;

    #pragma unroll 2
    for (int t = 0; t < T_STEPS; ++t) {
        const int buf = t & 1;

        // ---- butterfly on this step's partial (long pole starts first) ----
        float r = p;
        #pragma unroll
        for (int s = 1; s < 32; s <<= 1)
            r += __shfl_xor_sync(0xffffffffu, r, s);
        if (lane == 0)
            reinterpret_cast<float*>(&part4[buf][group])[wing] = r;

        // ==== SPECULATIVE spk=1 path (same work as R7 loop, hoisted) ========
        // post1 = fma(bm, post, 1); am1 = -A_MINUS*post1; ap = A_PLUS.
        const float post1 = fmaf(BETA_MINUS, post, 1.0f);
        const float am1   = -(A_MINUS * post1);

        u64 c01[KMAX], c23[KMAX];     // W(t) candidates (spk=1)
        u64 da = 0ull, db = 0ull;     // candidate dot with x_{t+1}
        #pragma unroll
        for (int k = 0; k < KMAX; ++k) {
            const u64 lw01 = ffma2(AP2, pre01[k], w01[k]);
            const u64 lw23 = ffma2(AP2, pre23[k], w23[k]);
            float lx, ly, lz, lw_, xx, xy, xz, xw;
            upk2(lw01, lx, ly);  upk2(lw23, lz, lw_);
            upk2(xc01[k], xx, xy); upk2(xc23[k], xz, xw);
            c01[k] = pk2(__saturatef(fmaf(am1, xx, lx)),
                         __saturatef(fmaf(am1, xy, ly)));
            c23[k] = pk2(__saturatef(fmaf(am1, xz, lz)),
                         __saturatef(fmaf(am1, xw, lw_)));
            da = ffma2(c01[k], xn01[k], da);
            db = ffma2(c23[k], xn23[k], db);
            // pre-trace recurrence (branch-independent)
            pre01[k] = ffma2(BP2, pre01[k], xc01[k]);
            pre23[k] = ffma2(BP2, pre23[k], xc23[k]);
        }
        float p1;
        {
            float aa, ab, ac, ad;
            upk2(da, aa, ab); upk2(db, ac, ad);
            p1 = (aa + ab) + (ac + ad);
        }
        // ==== END SPECULATIVE BLOCK =========================================

        neuron_bar(barid);

        // ---- I, LIF, verify prediction ----
        const float4 q = part4[buf][group];
        const float I = (q.x + q.y) + (q.z + q.w);

        syn = fmaf(ALPHA, syn, I);
        mem = fmaf(BETA, mem, syn) - spk_prev * THRESHOLD;
        const bool spkb = (mem > THRESHOLD);

        float spk;
        if (__builtin_expect(spkb, 1)) {
            // prediction hit: commit speculated state (register renames)
            spk  = 1.0f;
            post = post1;
            p    = p1;
            #pragma unroll
            for (int k = 0; k < KMAX; ++k) { w01[k] = c01[k]; w23[k] = c23[k]; }
        } else {
            // mispredict (rare; group-uniform): spk=0 update, bit-exact R7 path
            spk  = 0.0f;
            post = BETA_MINUS * post;
            const float am0 = -(A_MINUS * post);
            u64 ea = 0ull, eb = 0ull;
            #pragma unroll
            for (int k = 0; k < KMAX; ++k) {
                float wx, wy, wz, ww, xx, xy, xz, xw;
                upk2(w01[k], wx, wy); upk2(w23[k], wz, ww);
                upk2(xc01[k], xx, xy); upk2(xc23[k], xz, xw);
                w01[k] = pk2(__saturatef(fmaf(am0, xx, wx)),
                             __saturatef(fmaf(am0, xy, wy)));
                w23[k] = pk2(__saturatef(fmaf(am0, xz, wz)),
                             __saturatef(fmaf(am0, xw, ww)));
                ea = ffma2(w01[k], xn01[k], ea);
                eb = ffma2(w23[k], xn23[k], eb);
            }
            float aa, ab, ac, ad;
            upk2(ea, aa, ab); upk2(eb, ac, ad);
            p = (aa + ab) + (ac + ad);
        }

        // ---- store W_rec[t], rotate x, prefetch x_{t+2} ----
        #pragma unroll
        for (int k = 0; k < KMAX; ++k) {
            const bool act = (k == 0) || k1v;
            const int  c   = (k == 0) ? c0 : c1;
            if (act) stg_cs_v2b64(wptr + c, w01[k], w23[k]);
            xc01[k] = xn01[k]; xc23[k] = xn23[k];
            if (act && (t + 2 < T_STEPS)) {
                float4 xt = __ldg(xpf + c);
                xn01[k] = pk2(xt.x, xt.y);
                xn23[k] = pk2(xt.z, xt.w);
            }
        }

        // ---- scalar records (one thread per neuron) ----
        if (wing == 0 && lane == 0) {
            spkrec[sidx]  = spk;
            memrec[sidx]  = mem;
            synrec[sidx]  = syn;
            postrec[sidx] = post;
        }

        spk_prev = spk;
        wptr += (size_t)N_NEUR * CHUNKS;
        xpf  += CHUNKS;
        sidx += N_NEUR;
    }
}

extern "C" void kernel_launch(void* const* d_in, const int* in_sizes, int n_in,
                              void* d_out, int out_size)
{
    const float* image = (const float*)d_in[0];  // [256, 784] f32
    const float* W     = (const float*)d_in[1];  // [512, 784] f32
    float* out = (float*)d_out;
    (void)in_sizes; (void)n_in; (void)out_size;
    snn_pred<<<N_NEUR / NPB, NPB * WPN * 32>>>(image, W, out);
}

// round 11
// speedup vs baseline: 2.1962x; 1.4157x over previous
#include <cuda_runtime.h>

// SNN + STDP scan, 256 steps, 784 inputs, 512 neurons.
// R10 = R7 structure (no speculation - R8/R9 both regressed) with occupancy
// as the lever: 7 warps per neuron (224 lanes = 196 chunks padded), KMAX=1,
// 4 neurons x 7 warps = 896-thread blocks -> 28 warps/SM, 7 per SMSP (vs 4).
// Per-warp element work halves; the shfl/bar/LDS/LIF serial chain is now
// covered by 7-way warp interleaving instead of 4-way.
// Kept from R7: packed fma.rn.f32x2, per-neuron named barrier, fused
// next-step dot, double-buffered smem partials, __stcs streaming W_rec.

namespace {
constexpr int   T_STEPS = 256;
constexpr int   D_IN    = 784;
constexpr int   N_NEUR  = 512;
constexpr int   CHUNKS  = D_IN / 4;   // 196 float4 per row
constexpr int   WPN     = 7;          // warps per neuron (224 lanes)
constexpr int   NPB     = 4;          // neurons per block
constexpr int   NTHREADS = NPB * WPN * 32;   // 896
constexpr float ALPHA      = 0.9f;
constexpr float BETA       = 0.8f;
constexpr float THRESHOLD  = 1.0f;
constexpr float BETA_PLUS  = 0.9f;
constexpr float BETA_MINUS = 0.9f;
constexpr float A_PLUS     = 0.008f;
constexpr float A_MINUS    = 0.0066f;
}

using u64 = unsigned long long;

__device__ __forceinline__ u64 pk2(float lo, float hi) {
    u64 r; asm("mov.b64 %0, {%1, %2};" : "=l"(r) : "f"(lo), "f"(hi)); return r;
}
__device__ __forceinline__ void upk2(u64 v, float& lo, float& hi) {
    asm("mov.b64 {%0, %1}, %2;" : "=f"(lo), "=f"(hi) : "l"(v));
}
__device__ __forceinline__ u64 ffma2(u64 a, u64 b, u64 c) {
    u64 d; asm("fma.rn.f32x2 %0, %1, %2, %3;" : "=l"(d) : "l"(a), "l"(b), "l"(c));
    return d;
}
__device__ __forceinline__ void neuron_bar(int id) {
    asm volatile("bar.sync %0, %1;" :: "r"(id), "n"(WPN * 32) : "memory");
}
__device__ __forceinline__ void stg_cs_v2b64(void* p, u64 a, u64 b) {
    asm volatile("st.global.cs.v2.b64 [%0], {%1, %2};" :: "l"(p), "l"(a), "l"(b) : "memory");
}

__global__ __launch_bounds__(NTHREADS, 1)
void snn_occ7(const float* __restrict__ image,
              const float* __restrict__ W0,
              float* __restrict__ out)
{
    const int tid   = threadIdx.x;
    const int lane  = tid & 31;
    const int warp  = tid >> 5;            // 0..27
    const int group = warp / WPN;          // neuron slot, 0..3
    const int wing  = warp - group * WPN;  // 0..6
    const int n     = blockIdx.x * NPB + group;
    const int barid = group + 1;

    const int  c     = (wing << 5) + lane;   // chunk id, 0..223
    const bool valid = (c < CHUNKS);

    const float4 f4z = make_float4(0.f, 0.f, 0.f, 0.f);
    const u64 AP2 = pk2(A_PLUS, A_PLUS);
    const u64 BP2 = pk2(BETA_PLUS, BETA_PLUS);

    u64 w01, w23, pre01 = 0ull, pre23 = 0ull;
    u64 xc01, xc23, xn01, xn23;

    {   // load W chunk + x_0, x_1 (invalid lanes hold zeros; contribute 0)
        const float4* wrow = reinterpret_cast<const float4*>(W0) + (size_t)n * CHUNKS;
        const float4* xrow = reinterpret_cast<const float4*>(image);
        float4 tw = valid ? __ldg(wrow + c) : f4z;
        float4 a0 = valid ? __ldg(xrow + c) : f4z;
        float4 b0 = valid ? __ldg(xrow + CHUNKS + c) : f4z;
        w01  = pk2(tw.x, tw.y);  w23  = pk2(tw.z, tw.w);
        xc01 = pk2(a0.x, a0.y);  xc23 = pk2(a0.z, a0.w);
        xn01 = pk2(b0.x, b0.y);  xn23 = pk2(b0.z, b0.w);
    }
    const float4* xpf = reinterpret_cast<const float4*>(image) + 2 * (size_t)CHUNKS;

    // ---- prologue: per-lane partial of W0 . x_0 ----
    float p;
    {
        u64 m01 = ffma2(w01, xc01, 0ull);
        u64 m23 = ffma2(w23, xc23, 0ull);
        float aa, ab, ac, ad;
        upk2(m01, aa, ab); upk2(m23, ac, ad);
        p = (aa + ab) + (ac + ad);
    }

    // 8 slots per neuron (7 wings + zero pad), double buffered, 16B-aligned.
    __shared__ float part[2][NPB][8];
    if (tid < NPB) {            // zero the pad slot once
        part[0][tid][7] = 0.f;
        part[1][tid][7] = 0.f;
    }
    __syncthreads();

    float syn = 0.f, mem = 0.f, spk_prev = 0.f, post = 0.f;

    float* __restrict__ spkrec  = out + (size_t)T_STEPS * N_NEUR * D_IN;
    float* __restrict__ memrec  = spkrec  + T_STEPS * N_NEUR;
    float* __restrict__ synrec  = memrec  + T_STEPS * N_NEUR;
    float* __restrict__ postrec = synrec  + T_STEPS * N_NEUR;

    float4* wptr = reinterpret_cast<float4*>(out) + (size_t)n * CHUNKS;
    int sidx = n;

    #pragma unroll 2
    for (int t = 0; t < T_STEPS; ++t) {
        const int buf = t & 1;

        // ---- wing total: 5-step butterfly, lane0 stores one float ----
        float r = p;
        #pragma unroll
        for (int s = 1; s < 32; s <<= 1)
            r += __shfl_xor_sync(0xffffffffu, r, s);
        if (lane == 0) part[buf][group][wing] = r;
        neuron_bar(barid);

        // ---- I: 2 broadcast LDS.128 + 7 adds (slot 7 is 0) ----
        const float4 q0 = *reinterpret_cast<const float4*>(&part[buf][group][0]);
        const float4 q1 = *reinterpret_cast<const float4*>(&part[buf][group][4]);
        const float s0 = (q0.x + q0.y) + (q0.z + q0.w);
        const float s1 = (q1.x + q1.y) + (q1.z + q1.w);
        const float I  = s0 + s1;

        // ---- Synaptic LIF (replicated deterministically) ----
        syn = fmaf(ALPHA, syn, I);
        mem = fmaf(BETA, mem, syn) - spk_prev * THRESHOLD;
        const float spk = (mem > THRESHOLD) ? 1.0f : 0.0f;
        post = fmaf(BETA_MINUS, post, spk);

        const float ap  = A_PLUS * spk;
        const float am  = -(A_MINUS * post);
        const u64   ap2 = pk2(ap, ap);

        // ---- STDP update + clamp + store W_rec[t]; fused next dot ----
        {
            const u64 t01 = ffma2(ap2, pre01, w01);   // ltp base
            const u64 t23 = ffma2(ap2, pre23, w23);
            float tx, ty, tz, tw, xx, xy, xz, xw;
            upk2(t01, tx, ty); upk2(t23, tz, tw);
            upk2(xc01, xx, xy); upk2(xc23, xz, xw);
            w01 = pk2(__saturatef(fmaf(am, xx, tx)),
                      __saturatef(fmaf(am, xy, ty)));
            w23 = pk2(__saturatef(fmaf(am, xz, tz)),
                      __saturatef(fmaf(am, xw, tw)));
            if (valid) stg_cs_v2b64(wptr + c, w01, w23);

            // pre-trace recurrence (uses x_t)
            pre01 = ffma2(BP2, pre01, xc01);
            pre23 = ffma2(BP2, pre23, xc23);

            // fused dot for step t+1: W(t) . x_{t+1}
            u64 d01 = ffma2(w01, xn01, 0ull);
            u64 d23 = ffma2(w23, xn23, 0ull);
            float aa, ab, ac, ad;
            upk2(d01, aa, ab); upk2(d23, ac, ad);
            p = (aa + ab) + (ac + ad);
        }

        // ---- rotate x, prefetch x_{t+2} ----
        xc01 = xn01; xc23 = xn23;
        if (valid && (t + 2 < T_STEPS)) {
            float4 xt = __ldg(xpf + c);
            xn01 = pk2(xt.x, xt.y);
            xn23 = pk2(xt.z, xt.w);
        }

        // ---- scalar records (one thread per neuron) ----
        if (wing == 0 && lane == 0) {
            spkrec[sidx]  = spk;
            memrec[sidx]  = mem;
            synrec[sidx]  = syn;
            postrec[sidx] = post;
        }

        spk_prev = spk;
        wptr += (size_t)N_NEUR * CHUNKS;
        xpf  += CHUNKS;
        sidx += N_NEUR;
    }
}

extern "C" void kernel_launch(void* const* d_in, const int* in_sizes, int n_in,
                              void* d_out, int out_size)
{
    const float* image = (const float*)d_in[0];  // [256, 784] f32
    const float* W     = (const float*)d_in[1];  // [512, 784] f32
    float* out = (float*)d_out;
    (void)in_sizes; (void)n_in; (void)out_size;
    snn_occ7<<<N_NEUR / NPB, NTHREADS>>>(image, W, out);
}